// round 3
// baseline (speedup 1.0000x reference)
#include <cuda_runtime.h>
#include <math.h>

#define NB 8
#define NH 1024
#define NW 1024
#define HW (1 << 20)          // NH*NW
#define BHW (NB * HW)

#define NU 0.01f
#define DT 0.01f

// ------------------------- device scratch -------------------------
__device__ float  g_fa[2 * BHW];
__device__ float  g_fb[2 * BHW];
__device__ float  g_unew[BHW];
__device__ float  g_vnew[BHW];
__device__ float2 g_c1[BHW];
__device__ float2 g_c2[BHW];
__device__ float  g_pcorr[BHW];
__device__ float  g_partials[65536];
__device__ float  g_invnorm[16];

// ------------------------- helpers -------------------------
__device__ __forceinline__ float block_reduce_256(float v, float* red) {
    #pragma unroll
    for (int o = 16; o > 0; o >>= 1) v += __shfl_down_sync(0xffffffffu, v, o);
    int lane = threadIdx.x & 31, wid = threadIdx.x >> 5;
    if (lane == 0) red[wid] = v;
    __syncthreads();
    float s = 0.0f;
    if (wid == 0) {
        s = (lane < 8) ? red[lane] : 0.0f;
        #pragma unroll
        for (int o = 4; o > 0; o >>= 1) s += __shfl_down_sync(0xffffffffu, s, o);
    }
    return s;   // valid on thread 0
}

// ------------------------- smoothing (f += 0.1 * lap(f)) -------------------------
// mode 0: ext inputs -> g_fa ; mode 1: g_fa -> g_fb ; mode 2: g_fb -> g_fa (+partials)
__global__ void smooth_kernel(const float* __restrict__ su_ext,
                              const float* __restrict__ sv_ext, int mode) {
    int gid = blockIdx.x * 256 + threadIdx.x;           // over 2*BHW
    int fb  = gid >> 23;                                // BHW = 2^23
    int rem = gid & (BHW - 1);
    int b   = rem >> 20;
    int yx  = rem & (HW - 1);
    int y = yx >> 10, x = yx & 1023;

    const float* s;
    float* dst;
    if (mode == 0) { s = fb ? sv_ext : su_ext; dst = g_fa; }
    else if (mode == 1) { s = g_fa + (fb ? BHW : 0); dst = g_fb; }
    else { s = g_fb + (fb ? BHW : 0); dst = g_fa; }

    int bb = b << 20;
    float c  = s[bb + yx];
    float xp = s[bb + (y << 10) + ((x + 1) & 1023)];
    float xm = s[bb + (y << 10) + ((x - 1) & 1023)];
    float yp = s[bb + (((y + 1) & 1023) << 10) + x];
    float ym = s[bb + (((y - 1) & 1023) << 10) + x];
    float out = c + 0.1f * (xp + xm + yp + ym - 4.0f * c);
    dst[gid] = out;

    if (mode == 2) {
        __shared__ float red[8];
        float tot = block_reduce_256(out * out, red);
        if (threadIdx.x == 0) g_partials[blockIdx.x] = tot;
    }
}

__global__ void finalize_kernel() {
    int r = blockIdx.x;          // fb*8 + b
    float s = 0.0f;
    for (int i = threadIdx.x; i < 4096; i += 256) s += g_partials[r * 4096 + i];
    __shared__ float red[8];
    float tot = block_reduce_256(s, red);
    if (threadIdx.x == 0) {
        float nrm = sqrtf(tot);
        g_invnorm[r] = 1.0f / fmaxf(nrm, 1e-12f);
    }
}

// ------------------------- main update: u_new, v_new -------------------------
__global__ void update_kernel(const float* __restrict__ xin,
                              const float* __restrict__ beta) {
    int gid = blockIdx.x * 256 + threadIdx.x;           // over BHW
    int b  = gid >> 20;
    int yx = gid & (HW - 1);
    int y = yx >> 10, x = yx & 1023;

    const float* u = xin + (size_t)(b * 3 + 0) * HW;
    const float* v = xin + (size_t)(b * 3 + 1) * HW;
    const float* p = xin + (size_t)(b * 3 + 2) * HW;

    int ixp = (y << 10) | ((x + 1) & 1023);
    int ixm = (y << 10) | ((x - 1) & 1023);
    int iyp = (((y + 1) & 1023) << 10) | x;
    int iym = (((y - 1) & 1023) << 10) | x;

    float uc = u[yx], uxp = u[ixp], uxm = u[ixm], uyp = u[iyp], uym = u[iym];
    float vc = v[yx], vxp = v[ixp], vxm = v[ixm], vyp = v[iyp], vym = v[iym];
    float pxp = p[ixp], pxm = p[ixm], pyp = p[iyp], pym = p[iym];

    float ddx_u = 0.5f * (uxp - uxm), ddy_u = 0.5f * (uyp - uym);
    float ddx_v = 0.5f * (vxp - vxm), ddy_v = 0.5f * (vyp - vym);
    float adv_u = uc * ddx_u + vc * ddy_u;
    float adv_v = uc * ddx_v + vc * ddy_v;
    float lap_u = uxp + uxm + uyp + uym - 4.0f * uc;
    float lap_v = vxp + vxm + vyp + vym - 4.0f * vc;
    float dpdx = 0.5f * (pxp - pxm), dpdy = 0.5f * (pyp - pym);

    float sb = sqrtf(beta[b]);
    float fu = g_fa[(b << 20) + yx] * g_invnorm[b];
    float fv = g_fa[BHW + (b << 20) + yx] * g_invnorm[8 + b];

    g_unew[gid] = uc + DT * (-adv_u + NU * lap_u - dpdx) + sb * fu;
    g_vnew[gid] = vc + DT * (-adv_v + NU * lap_v - dpdy) + sb * fv;
}

// ------------------------- Stockham radix-2 FFT, N=1024, in shared -------------------------
// OTFFT-style Stockham (verified by hand on N=4 and N=8):
// stage t (s = 2^t):  q = idx mod s, p = idx div s
//   dst[2*idx - q]     = A + B
//   dst[2*idx - q + s] = w * (A - B),  w = exp(-2*pi*i * p*s / N) = tw[idx & ~(s-1)]
__device__ __forceinline__ void fft1024(float2* a, float2* bq, const float2* tw,
                                        int tid, bool inv) {
    float2* src = a;
    float2* dst = bq;
    #pragma unroll
    for (int t = 0; t < 10; t++) {
        int s = 1 << t;
        #pragma unroll
        for (int k = 0; k < 2; k++) {
            int idx = tid + k * 256;                 // idx in [0,512)
            int q   = idx & (s - 1);
            float2 A = src[idx];
            float2 Bv = src[idx + 512];
            float2 w = tw[idx & ~(s - 1)];
            if (inv) w.y = -w.y;
            float2 sum = make_float2(A.x + Bv.x, A.y + Bv.y);
            float2 dif = make_float2(A.x - Bv.x, A.y - Bv.y);
            int j0 = 2 * idx - q;
            dst[j0]     = sum;
            dst[j0 + s] = make_float2(dif.x * w.x - dif.y * w.y,
                                      dif.x * w.y + dif.y * w.x);
        }
        __syncthreads();
        float2* tmp = src; src = dst; dst = tmp;
    }
    // 10 stages -> result back in 'a'
}

__device__ __forceinline__ void build_twiddles(float2* tw, int tid) {
    #pragma unroll
    for (int k = 0; k < 2; k++) {
        int j = tid + k * 256;
        float sn, cs;
        sincosf(-6.283185307179586f * (float)j * (1.0f / 1024.0f), &sn, &cs);
        tw[j] = make_float2(cs, sn);
    }
}

// ------------------------- fwd FFT over x, with div computed on the fly -------------------------
__global__ void fft_fwd_div_kernel() {
    __shared__ float2 bufA[1024];
    __shared__ float2 bufB[1024];
    __shared__ float2 tw[512];
    __shared__ float  su[1024];

    int row = blockIdx.x;                    // b*NH + y
    int b = row >> 10, y = row & 1023;
    int tid = threadIdx.x;
    int rbase = row << 10;                   // row * NW

    #pragma unroll
    for (int k = 0; k < 4; k++) su[tid + k * 256] = g_unew[rbase + tid + k * 256];
    build_twiddles(tw, tid);
    __syncthreads();

    int vb = b << 20;
    int ypr = ((y + 1) & 1023) << 10, ymr = ((y - 1) & 1023) << 10;
    #pragma unroll
    for (int k = 0; k < 4; k++) {
        int x = tid + k * 256;
        float vp = g_vnew[vb + ypr + x];
        float vm = g_vnew[vb + ymr + x];
        float d = 0.5f * (su[(x + 1) & 1023] - su[(x - 1) & 1023]) + 0.5f * (vp - vm);
        bufA[x] = make_float2(d, 0.0f);
    }
    __syncthreads();

    fft1024(bufA, bufB, tw, tid, false);

    #pragma unroll
    for (int k = 0; k < 4; k++) { int x = tid + k * 256; g_c1[rbase + x] = bufA[x]; }
}

// ------------------------- tiled complex transposes (globals referenced DEVICE-side) -------------------------
// NOTE: __device__ globals must NOT be passed as kernel arguments from host code
// (host-side symbol reference yields a garbage pointer). Reference them here.
__global__ void transpose12_kernel() {   // g_c1 -> g_c2
    __shared__ float2 tile[32][33];
    int b = blockIdx.z;
    int x = blockIdx.x * 32 + threadIdx.x;
    int y = blockIdx.y * 32 + threadIdx.y;
    const float2* ib = g_c1 + b * HW;
    float2* ob = g_c2 + b * HW;
    #pragma unroll
    for (int j = 0; j < 32; j += 8)
        tile[threadIdx.y + j][threadIdx.x] = ib[(y + j) * NW + x];
    __syncthreads();
    int xo = blockIdx.y * 32 + threadIdx.x;
    int yo = blockIdx.x * 32 + threadIdx.y;
    #pragma unroll
    for (int j = 0; j < 32; j += 8)
        ob[(yo + j) * NH + xo] = tile[threadIdx.x][threadIdx.y + j];
}

__global__ void transpose21_kernel() {   // g_c2 -> g_c1
    __shared__ float2 tile[32][33];
    int b = blockIdx.z;
    int x = blockIdx.x * 32 + threadIdx.x;
    int y = blockIdx.y * 32 + threadIdx.y;
    const float2* ib = g_c2 + b * HW;
    float2* ob = g_c1 + b * HW;
    #pragma unroll
    for (int j = 0; j < 32; j += 8)
        tile[threadIdx.y + j][threadIdx.x] = ib[(y + j) * NW + x];
    __syncthreads();
    int xo = blockIdx.y * 32 + threadIdx.x;
    int yo = blockIdx.x * 32 + threadIdx.y;
    #pragma unroll
    for (int j = 0; j < 32; j += 8)
        ob[(yo + j) * NH + xo] = tile[threadIdx.x][threadIdx.y + j];
}

// ------------------------- fused: fwd FFT over y -> Poisson multiply -> inv FFT over y -------------------------
__global__ void fft_poisson_kernel() {
    __shared__ float2 bufA[1024];
    __shared__ float2 bufB[1024];
    __shared__ float2 tw[512];

    int row = blockIdx.x;                    // b*NW + kx   (transposed layout)
    int kx = row & 1023;
    int tid = threadIdx.x;
    int rbase = row << 10;

    #pragma unroll
    for (int k = 0; k < 4; k++) { int j = tid + k * 256; bufA[j] = g_c2[rbase + j]; }
    build_twiddles(tw, tid);
    __syncthreads();

    fft1024(bufA, bufB, tw, tid, false);

    float tkx = (float)min(kx, 1024 - kx);
    #pragma unroll
    for (int k = 0; k < 4; k++) {
        int ky = tid + k * 256;
        float tky = (float)min(ky, 1024 - ky);
        float k2 = tkx * tkx + tky * tky;
        float m = (kx == 0 && ky == 0) ? 0.0f
                                       : (-1.0f / (39.47841760435743f * k2));
        bufA[ky].x *= m;
        bufA[ky].y *= m;
    }
    __syncthreads();

    fft1024(bufA, bufB, tw, tid, true);

    const float sc = 1.0f / 1024.0f;
    #pragma unroll
    for (int k = 0; k < 4; k++) {
        int j = tid + k * 256;
        float2 v = bufA[j];
        g_c2[rbase + j] = make_float2(v.x * sc, v.y * sc);
    }
}

// ------------------------- inverse FFT over x, write real -> p_corr -------------------------
__global__ void fft_inv_real_kernel() {
    __shared__ float2 bufA[1024];
    __shared__ float2 bufB[1024];
    __shared__ float2 tw[512];

    int row = blockIdx.x;                    // b*NH + y
    int tid = threadIdx.x;
    int rbase = row << 10;

    #pragma unroll
    for (int k = 0; k < 4; k++) { int j = tid + k * 256; bufA[j] = g_c1[rbase + j]; }
    build_twiddles(tw, tid);
    __syncthreads();

    fft1024(bufA, bufB, tw, tid, true);

    const float sc = 1.0f / 1024.0f;
    #pragma unroll
    for (int k = 0; k < 4; k++) {
        int x = tid + k * 256;
        g_pcorr[rbase + x] = bufA[x].x * sc;
    }
}

// ------------------------- final: subtract pressure-correction gradient, stack output -------------------------
__global__ void final_kernel(const float* __restrict__ xin, float* __restrict__ out) {
    int gid = blockIdx.x * 256 + threadIdx.x;   // over BHW
    int b  = gid >> 20;
    int yx = gid & (HW - 1);
    int y = yx >> 10, x = yx & 1023;

    int ixp = (y << 10) | ((x + 1) & 1023);
    int ixm = (y << 10) | ((x - 1) & 1023);
    int iyp = (((y + 1) & 1023) << 10) | x;
    int iym = (((y - 1) & 1023) << 10) | x;

    int bb = b << 20;
    float pcc = g_pcorr[bb + yx];
    float pxp = g_pcorr[bb + ixp], pxm = g_pcorr[bb + ixm];
    float pyp = g_pcorr[bb + iyp], pym = g_pcorr[bb + iym];

    float uo = g_unew[gid] - 0.5f * (pxp - pxm);
    float vo = g_vnew[gid] - 0.5f * (pyp - pym);
    float po = xin[(size_t)(b * 3 + 2) * HW + yx] + pcc;

    out[(size_t)(b * 3 + 0) * HW + yx] = uo;
    out[(size_t)(b * 3 + 1) * HW + yx] = vo;
    out[(size_t)(b * 3 + 2) * HW + yx] = po;
}

// ------------------------- launch -------------------------
extern "C" void kernel_launch(void* const* d_in, const int* in_sizes, int n_in,
                              void* d_out, int out_size) {
    (void)in_sizes; (void)n_in; (void)out_size;
    const float* x    = (const float*)d_in[0];
    const float* beta = (const float*)d_in[1];
    const float* fu   = (const float*)d_in[2];
    const float* fv   = (const float*)d_in[3];
    float* out = (float*)d_out;

    const int TP = 256;
    // 3 smoothing iterations (ping-pong), last fused with norm partials
    smooth_kernel<<<2 * BHW / TP, TP>>>(fu, fv, 0);
    smooth_kernel<<<2 * BHW / TP, TP>>>(fu, fv, 1);
    smooth_kernel<<<2 * BHW / TP, TP>>>(fu, fv, 2);
    finalize_kernel<<<16, TP>>>();

    update_kernel<<<BHW / TP, TP>>>(x, beta);

    fft_fwd_div_kernel<<<NB * NH, TP>>>();
    {
        dim3 g(32, 32, NB), t(32, 8);
        transpose12_kernel<<<g, t>>>();
    }
    fft_poisson_kernel<<<NB * NW, TP>>>();
    {
        dim3 g(32, 32, NB), t(32, 8);
        transpose21_kernel<<<g, t>>>();
    }
    fft_inv_real_kernel<<<NB * NH, TP>>>();

    final_kernel<<<BHW / TP, TP>>>(x, out);
}

// round 4
// speedup vs baseline: 1.1327x; 1.1327x over previous
#include <cuda_runtime.h>
#include <math.h>

#define NB 8
#define NH 1024
#define NW 1024
#define HW (1 << 20)          // NH*NW
#define BHW (NB * HW)

#define NU 0.01f
#define DT 0.01f

// ------------------------- device scratch -------------------------
__device__ float  g_fa[2 * BHW];
__device__ float  g_unew[BHW];
__device__ float  g_vnew[BHW];
__device__ float2 g_c1[BHW];
__device__ float  g_pcorr[BHW];
__device__ float  g_partials[16384];
__device__ float  g_invnorm[16];

// ------------------------- helpers -------------------------
__device__ __forceinline__ float block_reduce_256(float v, float* red) {
    #pragma unroll
    for (int o = 16; o > 0; o >>= 1) v += __shfl_down_sync(0xffffffffu, v, o);
    int lane = threadIdx.x & 31, wid = threadIdx.x >> 5;
    if (lane == 0) red[wid] = v;
    __syncthreads();
    float s = 0.0f;
    if (wid == 0) {
        s = (lane < 8) ? red[lane] : 0.0f;
        #pragma unroll
        for (int o = 4; o > 0; o >>= 1) s += __shfl_down_sync(0xffffffffu, s, o);
    }
    return s;   // valid on thread 0
}

__device__ __forceinline__ void build_twiddles_256(float2* tw, int tid) {
    #pragma unroll
    for (int k = 0; k < 2; k++) {
        int j = tid + k * 256;
        float sn, cs;
        sincosf(-6.283185307179586f * (float)j * (1.0f / 1024.0f), &sn, &cs);
        tw[j] = make_float2(cs, sn);
    }
}

// ------------------------- fused 3x smoothing (f += 0.1*lap(f)) + norm partials -------------------------
// grid (1024, 16): blockIdx.y = fb*8+b ; blockIdx.x = 32x32 tile id
__global__ void smooth3_kernel(const float* __restrict__ su_ext,
                               const float* __restrict__ sv_ext) {
    __shared__ float t0[38][40];
    __shared__ float t1[38][40];
    __shared__ float red[8];
    int slab = blockIdx.y;
    int fb = slab >> 3, b = slab & 7;
    const float* src = (fb ? sv_ext : su_ext) + (b << 20);
    int tile = blockIdx.x;
    int ty0 = (tile >> 5) << 5;
    int tx0 = (tile & 31) << 5;
    int tid = threadIdx.x;

    for (int i = tid; i < 38 * 38; i += 256) {
        int ly = i / 38, lx = i - ly * 38;
        int gy = (ty0 + ly - 3) & 1023;
        int gx = (tx0 + lx - 3) & 1023;
        t0[ly][lx] = src[(gy << 10) + gx];
    }
    __syncthreads();
    for (int i = tid; i < 36 * 36; i += 256) {     // iter 1 -> t1, valid [1,37)
        int ly = i / 36, lx = i - ly * 36;
        ly += 1; lx += 1;
        float c = t0[ly][lx];
        t1[ly][lx] = c + 0.1f * (t0[ly][lx-1] + t0[ly][lx+1] + t0[ly-1][lx] + t0[ly+1][lx] - 4.0f * c);
    }
    __syncthreads();
    for (int i = tid; i < 34 * 34; i += 256) {     // iter 2 -> t0, valid [2,36)
        int ly = i / 34, lx = i - ly * 34;
        ly += 2; lx += 2;
        float c = t1[ly][lx];
        t0[ly][lx] = c + 0.1f * (t1[ly][lx-1] + t1[ly][lx+1] + t1[ly-1][lx] + t1[ly+1][lx] - 4.0f * c);
    }
    __syncthreads();
    float ss = 0.0f;
    float* dst = g_fa + fb * BHW + (b << 20);
    for (int i = tid; i < 1024; i += 256) {        // iter 3 -> out, valid [3,35)
        int ly = (i >> 5) + 3, lx = (i & 31) + 3;
        float c = t0[ly][lx];
        float o = c + 0.1f * (t0[ly][lx-1] + t0[ly][lx+1] + t0[ly-1][lx] + t0[ly+1][lx] - 4.0f * c);
        dst[((ty0 + ly - 3) << 10) + (tx0 + lx - 3)] = o;
        ss += o * o;
    }
    float tot = block_reduce_256(ss, red);
    if (tid == 0) g_partials[slab * 1024 + tile] = tot;
}

__global__ void finalize_kernel() {
    int r = blockIdx.x;          // fb*8 + b, 16 blocks
    float s = 0.0f;
    for (int i = threadIdx.x; i < 1024; i += 256) s += g_partials[r * 1024 + i];
    __shared__ float red[8];
    float tot = block_reduce_256(s, red);
    if (threadIdx.x == 0) {
        float nrm = sqrtf(tot);
        g_invnorm[r] = 1.0f / fmaxf(nrm, 1e-12f);
    }
}

// ------------------------- main update: u_new, v_new -------------------------
__global__ void update_kernel(const float* __restrict__ xin,
                              const float* __restrict__ beta) {
    int gid = blockIdx.x * 256 + threadIdx.x;           // over BHW
    int b  = gid >> 20;
    int yx = gid & (HW - 1);
    int y = yx >> 10, x = yx & 1023;

    const float* u = xin + (size_t)(b * 3 + 0) * HW;
    const float* v = xin + (size_t)(b * 3 + 1) * HW;
    const float* p = xin + (size_t)(b * 3 + 2) * HW;

    int ixp = (y << 10) | ((x + 1) & 1023);
    int ixm = (y << 10) | ((x - 1) & 1023);
    int iyp = (((y + 1) & 1023) << 10) | x;
    int iym = (((y - 1) & 1023) << 10) | x;

    float uc = u[yx], uxp = u[ixp], uxm = u[ixm], uyp = u[iyp], uym = u[iym];
    float vc = v[yx], vxp = v[ixp], vxm = v[ixm], vyp = v[iyp], vym = v[iym];
    float pxp = p[ixp], pxm = p[ixm], pyp = p[iyp], pym = p[iym];

    float adv_u = uc * 0.5f * (uxp - uxm) + vc * 0.5f * (uyp - uym);
    float adv_v = uc * 0.5f * (vxp - vxm) + vc * 0.5f * (vyp - vym);
    float lap_u = uxp + uxm + uyp + uym - 4.0f * uc;
    float lap_v = vxp + vxm + vyp + vym - 4.0f * vc;
    float dpdx = 0.5f * (pxp - pxm), dpdy = 0.5f * (pyp - pym);

    float sb = sqrtf(beta[b]);
    float fu = g_fa[(b << 20) + yx] * g_invnorm[b];
    float fv = g_fa[BHW + (b << 20) + yx] * g_invnorm[8 + b];

    g_unew[gid] = uc + DT * (-adv_u + NU * lap_u - dpdx) + sb * fu;
    g_vnew[gid] = vc + DT * (-adv_v + NU * lap_v - dpdy) + sb * fv;
}

// ------------------------- in-place DIF/DIT FFT pieces (N=1024) -------------------------
// tw[k] = exp(-2*pi*i*k/1024), k<512.
// DIF (natural in -> bit-reversed out), stages h=512..1:
//   q = bi mod h, j = 2*(bi-q)+q : {A,B}={s[j],s[j+h]} -> s[j]=A+B ; s[j+h]=(A-B)*tw[q<<t]
// DIT inverse (bit-reversed in -> natural out), stages h=1..512:
//   t2 = conj(tw[q<<(9-t)])*B ; s[j]=A+t2 ; s[j+h]=A-t2

// ------------------------- fwd FFT over x (div computed on the fly), bitrev-x output -------------------------
__global__ void fft_fwd_div_kernel() {
    __shared__ float2 buf[1024];
    __shared__ float2 tw[512];
    __shared__ float  su[1024];

    int row = blockIdx.x;                    // b*NH + y
    int b = row >> 10, y = row & 1023;
    int tid = threadIdx.x;                   // 256
    int rbase = row << 10;

    #pragma unroll
    for (int k = 0; k < 4; k++) su[tid + k * 256] = g_unew[rbase + tid + k * 256];
    build_twiddles_256(tw, tid);
    __syncthreads();

    int vb = b << 20;
    int ypr = ((y + 1) & 1023) << 10, ymr = ((y - 1) & 1023) << 10;
    #pragma unroll
    for (int k = 0; k < 4; k++) {
        int x = tid + k * 256;
        float vp = g_vnew[vb + ypr + x];
        float vm = g_vnew[vb + ymr + x];
        float d = 0.5f * (su[(x + 1) & 1023] - su[(x - 1) & 1023]) + 0.5f * (vp - vm);
        buf[x] = make_float2(d, 0.0f);
    }
    __syncthreads();

    #pragma unroll
    for (int t = 0; t < 10; t++) {
        int h = 512 >> t;
        #pragma unroll
        for (int k = 0; k < 2; k++) {
            int bi = tid + k * 256;
            int q = bi & (h - 1);
            int j = ((bi - q) << 1) + q;
            float2 A = buf[j], B = buf[j + h];
            float2 w = tw[q << t];
            buf[j] = make_float2(A.x + B.x, A.y + B.y);
            float dx = A.x - B.x, dy = A.y - B.y;
            buf[j + h] = make_float2(dx * w.x - dy * w.y, dx * w.y + dy * w.x);
        }
        __syncthreads();
    }

    #pragma unroll
    for (int k = 0; k < 4; k++) { int x = tid + k * 256; g_c1[rbase + x] = buf[x]; }
}

// ------------------------- fused column pipeline: fwd FFT(y) -> Poisson -> inv FFT(y) -------------------------
// 4 columns per block, in place in g_c1 (bitrev-x positions). 256 threads.
__global__ void fft_col_poisson_kernel() {
    __shared__ float2 s[4096];               // [y][c], linear y*4+c : 32KB
    __shared__ float2 tw[512];

    int blk = blockIdx.x;                    // b*256 + xg
    int b = blk >> 8, xg = blk & 255;
    int x0 = xg << 2;
    int tid = threadIdx.x;                   // 256
    float2* base = g_c1 + (b << 20);

    build_twiddles_256(tw, tid);

    int c = tid & 3, yy = tid >> 2;          // yy in [0,64)
    #pragma unroll
    for (int m = 0; m < 16; m++) {
        int y = yy + (m << 6);
        s[(y << 2) + c] = base[(y << 10) + x0 + c];
    }
    __syncthreads();

    // forward DIF along y (natural -> bit-reversed)
    #pragma unroll
    for (int t = 0; t < 10; t++) {
        int h = 512 >> t;
        #pragma unroll
        for (int k = 0; k < 8; k++) {
            int bi = (tid >> 2) + (k << 6);  // [0,512)
            int q = bi & (h - 1);
            int j = ((bi - q) << 1) + q;
            int a0 = (j << 2) + c, a1 = ((j + h) << 2) + c;
            float2 A = s[a0], B = s[a1];
            float2 w = tw[q << t];
            s[a0] = make_float2(A.x + B.x, A.y + B.y);
            float dx = A.x - B.x, dy = A.y - B.y;
            s[a1] = make_float2(dx * w.x - dy * w.y, dx * w.y + dy * w.x);
        }
        __syncthreads();
    }

    // Poisson multiplier at bit-reversed coords; fold 1/1024 of the normalization in
    int kx = __brev((unsigned)(x0 + c)) >> 22;
    float tkx = (float)min(kx, 1024 - kx);
    #pragma unroll
    for (int m = 0; m < 16; m++) {
        int r = yy + (m << 6);
        int ky = __brev((unsigned)r) >> 22;
        float tky = (float)min(ky, 1024 - ky);
        float k2 = tkx * tkx + tky * tky;
        float mm = (kx == 0 && ky == 0) ? 0.0f
                 : (-1.0f / (39.47841760435743f * k2)) * (1.0f / 1024.0f);
        int a = (r << 2) + c;
        s[a].x *= mm; s[a].y *= mm;
    }
    __syncthreads();

    // inverse DIT along y (bit-reversed -> natural)
    #pragma unroll
    for (int t = 0; t < 10; t++) {
        int h = 1 << t;
        #pragma unroll
        for (int k = 0; k < 8; k++) {
            int bi = (tid >> 2) + (k << 6);
            int q = bi & (h - 1);
            int j = ((bi - q) << 1) + q;
            int a0 = (j << 2) + c, a1 = ((j + h) << 2) + c;
            float2 A = s[a0], B = s[a1];
            float2 w = tw[q << (9 - t)];     // use conj(w)
            float tx = w.x * B.x + w.y * B.y;
            float ty = w.x * B.y - w.y * B.x;
            s[a0] = make_float2(A.x + tx, A.y + ty);
            s[a1] = make_float2(A.x - tx, A.y - ty);
        }
        __syncthreads();
    }

    #pragma unroll
    for (int m = 0; m < 16; m++) {
        int y = yy + (m << 6);
        base[(y << 10) + x0 + c] = s[(y << 2) + c];
    }
}

// ------------------------- inverse FFT over x (bitrev-x in), write real -> p_corr -------------------------
__global__ void fft_inv_real_kernel() {
    __shared__ float2 buf[1024];
    __shared__ float2 tw[512];

    int row = blockIdx.x;                    // b*NH + y
    int tid = threadIdx.x;                   // 256
    int rbase = row << 10;

    #pragma unroll
    for (int k = 0; k < 4; k++) { int j = tid + k * 256; buf[j] = g_c1[rbase + j]; }
    build_twiddles_256(tw, tid);
    __syncthreads();

    #pragma unroll
    for (int t = 0; t < 10; t++) {
        int h = 1 << t;
        #pragma unroll
        for (int k = 0; k < 2; k++) {
            int bi = tid + k * 256;
            int q = bi & (h - 1);
            int j = ((bi - q) << 1) + q;
            float2 A = buf[j], B = buf[j + h];
            float2 w = tw[q << (9 - t)];     // conj
            float tx = w.x * B.x + w.y * B.y;
            float ty = w.x * B.y - w.y * B.x;
            buf[j]     = make_float2(A.x + tx, A.y + ty);
            buf[j + h] = make_float2(A.x - tx, A.y - ty);
        }
        __syncthreads();
    }

    const float sc = 1.0f / 1024.0f;
    #pragma unroll
    for (int k = 0; k < 4; k++) {
        int x = tid + k * 256;
        g_pcorr[rbase + x] = buf[x].x * sc;
    }
}

// ------------------------- final: subtract grad(p_corr), stack output -------------------------
__global__ void final_kernel(const float* __restrict__ xin, float* __restrict__ out) {
    int gid = blockIdx.x * 256 + threadIdx.x;   // over BHW
    int b  = gid >> 20;
    int yx = gid & (HW - 1);
    int y = yx >> 10, x = yx & 1023;

    int ixp = (y << 10) | ((x + 1) & 1023);
    int ixm = (y << 10) | ((x - 1) & 1023);
    int iyp = (((y + 1) & 1023) << 10) | x;
    int iym = (((y - 1) & 1023) << 10) | x;

    int bb = b << 20;
    float pcc = g_pcorr[bb + yx];
    float pxp = g_pcorr[bb + ixp], pxm = g_pcorr[bb + ixm];
    float pyp = g_pcorr[bb + iyp], pym = g_pcorr[bb + iym];

    float uo = g_unew[gid] - 0.5f * (pxp - pxm);
    float vo = g_vnew[gid] - 0.5f * (pyp - pym);
    float po = xin[(size_t)(b * 3 + 2) * HW + yx] + pcc;

    out[(size_t)(b * 3 + 0) * HW + yx] = uo;
    out[(size_t)(b * 3 + 1) * HW + yx] = vo;
    out[(size_t)(b * 3 + 2) * HW + yx] = po;
}

// ------------------------- launch -------------------------
extern "C" void kernel_launch(void* const* d_in, const int* in_sizes, int n_in,
                              void* d_out, int out_size) {
    (void)in_sizes; (void)n_in; (void)out_size;
    const float* x    = (const float*)d_in[0];
    const float* beta = (const float*)d_in[1];
    const float* fu   = (const float*)d_in[2];
    const float* fv   = (const float*)d_in[3];
    float* out = (float*)d_out;

    smooth3_kernel<<<dim3(1024, 16), 256>>>(fu, fv);
    finalize_kernel<<<16, 256>>>();
    update_kernel<<<BHW / 256, 256>>>(x, beta);
    fft_fwd_div_kernel<<<NB * NH, 256>>>();
    fft_col_poisson_kernel<<<NB * 256, 256>>>();
    fft_inv_real_kernel<<<NB * NH, 256>>>();
    final_kernel<<<BHW / 256, 256>>>(x, out);
}

// round 5
// speedup vs baseline: 1.3253x; 1.1700x over previous
#include <cuda_runtime.h>
#include <math.h>

#define NB 8
#define NH 1024
#define NW 1024
#define HW (1 << 20)
#define BHW (NB * HW)

#define NU 0.01f
#define DT 0.01f

#define PD(i) ((i) + ((i) >> 5))   // bank-conflict padding for power-of-2 strides

// ------------------------- device scratch -------------------------
__device__ float  g_fa[2 * BHW];
__device__ float  g_unew[BHW];
__device__ float  g_vnew[BHW];
__device__ float2 g_c1[BHW];
__device__ float  g_pcorr[BHW];
__device__ float  g_partials[16384];
__device__ float  g_invnorm[16];

// ------------------------- helpers -------------------------
__device__ __forceinline__ float block_reduce_256(float v, float* red) {
    #pragma unroll
    for (int o = 16; o > 0; o >>= 1) v += __shfl_down_sync(0xffffffffu, v, o);
    int lane = threadIdx.x & 31, wid = threadIdx.x >> 5;
    if (lane == 0) red[wid] = v;
    __syncthreads();
    float s = 0.0f;
    if (wid == 0) {
        s = (lane < 8) ? red[lane] : 0.0f;
        #pragma unroll
        for (int o = 4; o > 0; o >>= 1) s += __shfl_down_sync(0xffffffffu, s, o);
    }
    return s;
}

__device__ __forceinline__ void build_tw(float* twR, float* twI, int tid) {
    #pragma unroll
    for (int k = 0; k < 2; k++) {
        int j = tid + k * 256;
        float sn, cs;
        sincosf(-6.283185307179586f * (float)j * (1.0f / 1024.0f), &sn, &cs);
        twR[PD(j)] = cs; twI[PD(j)] = sn;
    }
}

// Fused double DIF stage (t, t+1), forward. Operates on one quadruple.
// h = 512>>t, h2 = h>>1; q = bi & (h2-1); B = bi >> (8-t); adr = B*2h + q.
#define FWD_DOUBLE(sR, sI, twR, twI, bi, t)                                     \
{                                                                               \
    const int h = 512 >> (t), h2 = h >> 1;                                      \
    int q = (bi) & (h2 - 1);                                                    \
    int B = (bi) >> (8 - (t));                                                  \
    int adr = B * (h << 1) + q;                                                 \
    int a0 = PD(adr), a1 = PD(adr + h2), a2 = PD(adr + h), a3 = PD(adr + h + h2); \
    float x0r = sR[a0], x0i = sI[a0], x1r = sR[a1], x1i = sI[a1];               \
    float x2r = sR[a2], x2i = sI[a2], x3r = sR[a3], x3i = sI[a3];               \
    int i0 = PD(q << (t)), i1 = PD(q << ((t) + 1));                             \
    float w0r = twR[i0], w0i = twI[i0];                                         \
    float w1r = twR[i1], w1i = twI[i1];                                         \
    float u0r = x0r + x2r, u0i = x0i + x2i;                                     \
    float d0r = x0r - x2r, d0i = x0i - x2i;                                     \
    float e0r = d0r * w0r - d0i * w0i, e0i = d0r * w0i + d0i * w0r;             \
    float u1r = x1r + x3r, u1i = x1i + x3i;                                     \
    float d1r = x1r - x3r, d1i = x1i - x3i;                                     \
    float e1r = d1r * w0i + d1i * w0r, e1i = -d1r * w0r + d1i * w0i;            \
    sR[a0] = u0r + u1r; sI[a0] = u0i + u1i;                                     \
    float f0r = u0r - u1r, f0i = u0i - u1i;                                     \
    sR[a1] = f0r * w1r - f0i * w1i; sI[a1] = f0r * w1i + f0i * w1r;             \
    sR[a2] = e0r + e1r; sI[a2] = e0i + e1i;                                     \
    float f1r = e0r - e1r, f1i = e0i - e1i;                                     \
    sR[a3] = f1r * w1r - f1i * w1i; sI[a3] = f1r * w1i + f1i * w1r;             \
}

// Fused double DIT stage (t, t+1), inverse (uses conj twiddles).
// h = 1<<t; q = bi & (h-1); B = bi >> t; e0 = B*4h + q.
#define INV_DOUBLE(sR, sI, twR, twI, bi, t)                                     \
{                                                                               \
    const int h = 1 << (t);                                                     \
    int q = (bi) & (h - 1);                                                     \
    int B = (bi) >> (t);                                                        \
    int e0 = B * (h << 2) + q;                                                  \
    int a0 = PD(e0), a1 = PD(e0 + h), a2 = PD(e0 + 2 * h), a3 = PD(e0 + 3 * h); \
    float x0r = sR[a0], x0i = sI[a0], x1r = sR[a1], x1i = sI[a1];               \
    float x2r = sR[a2], x2i = sI[a2], x3r = sR[a3], x3i = sI[a3];               \
    int i0 = PD(q << (9 - (t))), i1 = PD(q << (8 - (t)));                       \
    float c0r = twR[i0], c0i = -twI[i0];                                        \
    float c1r = twR[i1], c1i = -twI[i1];                                        \
    float t1r = c0r * x1r - c0i * x1i, t1i = c0r * x1i + c0i * x1r;             \
    float b0r = x0r + t1r, b0i = x0i + t1i, b1r = x0r - t1r, b1i = x0i - t1i;   \
    float t3r = c0r * x3r - c0i * x3i, t3i = c0r * x3i + c0i * x3r;             \
    float b2r = x2r + t3r, b2i = x2i + t3i, b3r = x2r - t3r, b3i = x2i - t3i;   \
    float t2r = c1r * b2r - c1i * b2i, t2i = c1r * b2i + c1i * b2r;             \
    sR[a0] = b0r + t2r; sI[a0] = b0i + t2i;                                     \
    sR[a2] = b0r - t2r; sI[a2] = b0i - t2i;                                     \
    float gr = -c1i, gi = c1r;                                                  \
    float t4r = gr * b3r - gi * b3i, t4i = gr * b3i + gi * b3r;                 \
    sR[a1] = b1r + t4r; sI[a1] = b1i + t4i;                                     \
    sR[a3] = b1r - t4r; sI[a3] = b1i - t4i;                                     \
}

// ------------------------- fused 3x smoothing + norm partials -------------------------
__global__ void smooth3_kernel(const float* __restrict__ su_ext,
                               const float* __restrict__ sv_ext) {
    __shared__ float t0[38][40];
    __shared__ float t1[38][40];
    __shared__ float red[8];
    int slab = blockIdx.y;
    int fb = slab >> 3, b = slab & 7;
    const float* src = (fb ? sv_ext : su_ext) + (b << 20);
    int tile = blockIdx.x;
    int ty0 = (tile >> 5) << 5;
    int tx0 = (tile & 31) << 5;
    int tid = threadIdx.x;

    for (int i = tid; i < 38 * 38; i += 256) {
        int ly = i / 38, lx = i - ly * 38;
        int gy = (ty0 + ly - 3) & 1023;
        int gx = (tx0 + lx - 3) & 1023;
        t0[ly][lx] = src[(gy << 10) + gx];
    }
    __syncthreads();
    for (int i = tid; i < 36 * 36; i += 256) {
        int ly = i / 36, lx = i - ly * 36;
        ly += 1; lx += 1;
        float c = t0[ly][lx];
        t1[ly][lx] = c + 0.1f * (t0[ly][lx-1] + t0[ly][lx+1] + t0[ly-1][lx] + t0[ly+1][lx] - 4.0f * c);
    }
    __syncthreads();
    for (int i = tid; i < 34 * 34; i += 256) {
        int ly = i / 34, lx = i - ly * 34;
        ly += 2; lx += 2;
        float c = t1[ly][lx];
        t0[ly][lx] = c + 0.1f * (t1[ly][lx-1] + t1[ly][lx+1] + t1[ly-1][lx] + t1[ly+1][lx] - 4.0f * c);
    }
    __syncthreads();
    float ss = 0.0f;
    float* dst = g_fa + fb * BHW + (b << 20);
    for (int i = tid; i < 1024; i += 256) {
        int ly = (i >> 5) + 3, lx = (i & 31) + 3;
        float c = t0[ly][lx];
        float o = c + 0.1f * (t0[ly][lx-1] + t0[ly][lx+1] + t0[ly-1][lx] + t0[ly+1][lx] - 4.0f * c);
        dst[((ty0 + ly - 3) << 10) + (tx0 + lx - 3)] = o;
        ss += o * o;
    }
    float tot = block_reduce_256(ss, red);
    if (tid == 0) g_partials[slab * 1024 + tile] = tot;
}

__global__ void finalize_kernel() {
    int r = blockIdx.x;
    float s = 0.0f;
    for (int i = threadIdx.x; i < 1024; i += 256) s += g_partials[r * 1024 + i];
    __shared__ float red[8];
    float tot = block_reduce_256(s, red);
    if (threadIdx.x == 0) {
        float nrm = sqrtf(tot);
        g_invnorm[r] = 1.0f / fmaxf(nrm, 1e-12f);
    }
}

// ------------------------- main update -------------------------
__global__ void update_kernel(const float* __restrict__ xin,
                              const float* __restrict__ beta) {
    int gid = blockIdx.x * 256 + threadIdx.x;
    int b  = gid >> 20;
    int yx = gid & (HW - 1);
    int y = yx >> 10, x = yx & 1023;

    const float* u = xin + (size_t)(b * 3 + 0) * HW;
    const float* v = xin + (size_t)(b * 3 + 1) * HW;
    const float* p = xin + (size_t)(b * 3 + 2) * HW;

    int ixp = (y << 10) | ((x + 1) & 1023);
    int ixm = (y << 10) | ((x - 1) & 1023);
    int iyp = (((y + 1) & 1023) << 10) | x;
    int iym = (((y - 1) & 1023) << 10) | x;

    float uc = u[yx], uxp = u[ixp], uxm = u[ixm], uyp = u[iyp], uym = u[iym];
    float vc = v[yx], vxp = v[ixp], vxm = v[ixm], vyp = v[iyp], vym = v[iym];
    float pxp = p[ixp], pxm = p[ixm], pyp = p[iyp], pym = p[iym];

    float adv_u = uc * 0.5f * (uxp - uxm) + vc * 0.5f * (uyp - uym);
    float adv_v = uc * 0.5f * (vxp - vxm) + vc * 0.5f * (vyp - vym);
    float lap_u = uxp + uxm + uyp + uym - 4.0f * uc;
    float lap_v = vxp + vxm + vyp + vym - 4.0f * vc;
    float dpdx = 0.5f * (pxp - pxm), dpdy = 0.5f * (pyp - pym);

    float sb = sqrtf(beta[b]);
    float fu = g_fa[(b << 20) + yx] * g_invnorm[b];
    float fv = g_fa[BHW + (b << 20) + yx] * g_invnorm[8 + b];

    g_unew[gid] = uc + DT * (-adv_u + NU * lap_u - dpdx) + sb * fu;
    g_vnew[gid] = vc + DT * (-adv_v + NU * lap_v - dpdy) + sb * fv;
}

// ------------------------- fwd FFT over x (div on the fly) -> bitrev-x order -------------------------
__global__ void fft_fwd_div_kernel() {
    __shared__ float sR[1056], sI[1056];
    __shared__ float twR[528], twI[528];
    __shared__ float su[1024];

    int row = blockIdx.x;
    int b = row >> 10, y = row & 1023;
    int tid = threadIdx.x;
    int rbase = row << 10;

    build_tw(twR, twI, tid);
    #pragma unroll
    for (int k = 0; k < 4; k++) su[tid + k * 256] = g_unew[rbase + tid + k * 256];
    __syncthreads();

    int vb = b << 20;
    int ypr = ((y + 1) & 1023) << 10, ymr = ((y - 1) & 1023) << 10;
    #pragma unroll
    for (int k = 0; k < 4; k++) {
        int x = tid + k * 256;
        float d = 0.5f * (su[(x + 1) & 1023] - su[(x - 1) & 1023])
                + 0.5f * (g_vnew[vb + ypr + x] - g_vnew[vb + ymr + x]);
        sR[PD(x)] = d; sI[PD(x)] = 0.0f;
    }
    __syncthreads();

    #pragma unroll
    for (int t = 0; t < 10; t += 2) {
        FWD_DOUBLE(sR, sI, twR, twI, tid, t);
        __syncthreads();
    }

    #pragma unroll
    for (int k = 0; k < 4; k++) {
        int x = tid + k * 256;
        g_c1[rbase + x] = make_float2(sR[PD(x)], sI[PD(x)]);
    }
}

// ------------------------- fused column pipeline: FFT(y) -> Poisson -> iFFT(y) -------------------------
#define CS 1057
__global__ void fft_col_poisson_kernel() {
    __shared__ float sR[4 * CS], sI[4 * CS];
    __shared__ float twR[528], twI[528];

    int blk = blockIdx.x;                    // b*256 + xg
    int b = blk >> 8, xg = blk & 255;
    int x0 = xg << 2;
    int tid = threadIdx.x;
    float2* base = g_c1 + (b << 20);

    build_tw(twR, twI, tid);

    int c = tid & 3, yy = tid >> 2;          // load/store + multiply mapping
    #pragma unroll
    for (int m = 0; m < 16; m++) {
        int y = yy + (m << 6);
        float2 v = base[(y << 10) + x0 + c];
        sR[c * CS + PD(y)] = v.x; sI[c * CS + PD(y)] = v.y;
    }
    __syncthreads();

    int cc = tid >> 6, r = tid & 63;         // butterfly mapping: 64 threads per column
    float* cR = sR + cc * CS;
    float* cI = sI + cc * CS;

    #pragma unroll
    for (int t = 0; t < 10; t += 2) {
        #pragma unroll
        for (int k = 0; k < 4; k++) {
            int bi = r + (k << 6);
            FWD_DOUBLE(cR, cI, twR, twI, bi, t);
        }
        __syncthreads();
    }

    // Poisson multiplier at bit-reversed coords (fold 1/1024)
    int kx = __brev((unsigned)(x0 + c)) >> 22;
    float tkx = (float)min(kx, 1024 - kx);
    #pragma unroll
    for (int m = 0; m < 16; m++) {
        int ry = yy + (m << 6);
        int ky = __brev((unsigned)ry) >> 22;
        float tky = (float)min(ky, 1024 - ky);
        float k2 = tkx * tkx + tky * tky;
        float mm = (kx == 0 && ky == 0) ? 0.0f
                 : (-1.0f / (39.47841760435743f * k2)) * (1.0f / 1024.0f);
        int a = c * CS + PD(ry);
        sR[a] *= mm; sI[a] *= mm;
    }
    __syncthreads();

    #pragma unroll
    for (int t = 0; t < 10; t += 2) {
        #pragma unroll
        for (int k = 0; k < 4; k++) {
            int bi = r + (k << 6);
            INV_DOUBLE(cR, cI, twR, twI, bi, t);
        }
        __syncthreads();
    }

    #pragma unroll
    for (int m = 0; m < 16; m++) {
        int y = yy + (m << 6);
        base[(y << 10) + x0 + c] = make_float2(sR[c * CS + PD(y)], sI[c * CS + PD(y)]);
    }
}

// ------------------------- inverse FFT over x (bitrev-x in) -> real p_corr -------------------------
__global__ void fft_inv_real_kernel() {
    __shared__ float sR[1056], sI[1056];
    __shared__ float twR[528], twI[528];

    int row = blockIdx.x;
    int tid = threadIdx.x;
    int rbase = row << 10;

    build_tw(twR, twI, tid);
    #pragma unroll
    for (int k = 0; k < 4; k++) {
        int j = tid + k * 256;
        float2 v = g_c1[rbase + j];
        sR[PD(j)] = v.x; sI[PD(j)] = v.y;
    }
    __syncthreads();

    #pragma unroll
    for (int t = 0; t < 10; t += 2) {
        INV_DOUBLE(sR, sI, twR, twI, tid, t);
        __syncthreads();
    }

    const float sc = 1.0f / 1024.0f;
    #pragma unroll
    for (int k = 0; k < 4; k++) {
        int x = tid + k * 256;
        g_pcorr[rbase + x] = sR[PD(x)] * sc;
    }
}

// ------------------------- final: subtract grad(p_corr), stack output -------------------------
__global__ void final_kernel(const float* __restrict__ xin, float* __restrict__ out) {
    int gid = blockIdx.x * 256 + threadIdx.x;
    int b  = gid >> 20;
    int yx = gid & (HW - 1);
    int y = yx >> 10, x = yx & 1023;

    int ixp = (y << 10) | ((x + 1) & 1023);
    int ixm = (y << 10) | ((x - 1) & 1023);
    int iyp = (((y + 1) & 1023) << 10) | x;
    int iym = (((y - 1) & 1023) << 10) | x;

    int bb = b << 20;
    float pcc = g_pcorr[bb + yx];
    float pxp = g_pcorr[bb + ixp], pxm = g_pcorr[bb + ixm];
    float pyp = g_pcorr[bb + iyp], pym = g_pcorr[bb + iym];

    float uo = g_unew[gid] - 0.5f * (pxp - pxm);
    float vo = g_vnew[gid] - 0.5f * (pyp - pym);
    float po = xin[(size_t)(b * 3 + 2) * HW + yx] + pcc;

    out[(size_t)(b * 3 + 0) * HW + yx] = uo;
    out[(size_t)(b * 3 + 1) * HW + yx] = vo;
    out[(size_t)(b * 3 + 2) * HW + yx] = po;
}

// ------------------------- launch -------------------------
extern "C" void kernel_launch(void* const* d_in, const int* in_sizes, int n_in,
                              void* d_out, int out_size) {
    (void)in_sizes; (void)n_in; (void)out_size;
    const float* x    = (const float*)d_in[0];
    const float* beta = (const float*)d_in[1];
    const float* fu   = (const float*)d_in[2];
    const float* fv   = (const float*)d_in[3];
    float* out = (float*)d_out;

    smooth3_kernel<<<dim3(1024, 16), 256>>>(fu, fv);
    finalize_kernel<<<16, 256>>>();
    update_kernel<<<BHW / 256, 256>>>(x, beta);
    fft_fwd_div_kernel<<<NB * NH, 256>>>();
    fft_col_poisson_kernel<<<NB * 256, 256>>>();
    fft_inv_real_kernel<<<NB * NH, 256>>>();
    final_kernel<<<BHW / 256, 256>>>(x, out);
}

// round 6
// speedup vs baseline: 1.7343x; 1.3086x over previous
#include <cuda_runtime.h>
#include <math.h>

#define NB 8
#define NH 1024
#define NW 1024
#define HW (1 << 20)
#define BHW (NB * HW)

#define NU 0.01f
#define DT 0.01f

#define PD(i) ((i) + ((i) >> 5))

#define C1ROW 520                      // compact spectral row stride (513 used)
#define C1BATCH (1024 * C1ROW)

// ------------------------- device scratch -------------------------
__device__ float  g_fa[2 * BHW];
__device__ float  g_unew[BHW];
__device__ float  g_vnew[BHW];
__device__ float2 g_c1[NB * C1BATCH];  // compact half-spectra: slot cc<512 -> storage j=2cc; cc=512 -> j=1
__device__ float  g_pcorr[BHW];
__device__ float  g_partials[16384];
__device__ float  g_invnorm[16];

// ------------------------- helpers -------------------------
__device__ __forceinline__ float block_reduce_256(float v, float* red) {
    #pragma unroll
    for (int o = 16; o > 0; o >>= 1) v += __shfl_down_sync(0xffffffffu, v, o);
    int lane = threadIdx.x & 31, wid = threadIdx.x >> 5;
    if (lane == 0) red[wid] = v;
    __syncthreads();
    float s = 0.0f;
    if (wid == 0) {
        s = (lane < 8) ? red[lane] : 0.0f;
        #pragma unroll
        for (int o = 4; o > 0; o >>= 1) s += __shfl_down_sync(0xffffffffu, s, o);
    }
    return s;
}

__device__ __forceinline__ void build_tw(float* twR, float* twI, int tid) {
    #pragma unroll
    for (int k = 0; k < 2; k++) {
        int j = tid + k * 256;
        float sn, cs;
        sincosf(-6.283185307179586f * (float)j * (1.0f / 1024.0f), &sn, &cs);
        twR[PD(j)] = cs; twI[PD(j)] = sn;
    }
}

__device__ __forceinline__ int brev10(int v) { return (int)(__brev((unsigned)v) >> 22); }

// Fused double DIF stage (t, t+1), forward.
#define FWD_DOUBLE(sR, sI, twR, twI, bi, t)                                     \
{                                                                               \
    const int h = 512 >> (t), h2 = h >> 1;                                      \
    int q = (bi) & (h2 - 1);                                                    \
    int B = (bi) >> (8 - (t));                                                  \
    int adr = B * (h << 1) + q;                                                 \
    int a0 = PD(adr), a1 = PD(adr + h2), a2 = PD(adr + h), a3 = PD(adr + h + h2); \
    float x0r = sR[a0], x0i = sI[a0], x1r = sR[a1], x1i = sI[a1];               \
    float x2r = sR[a2], x2i = sI[a2], x3r = sR[a3], x3i = sI[a3];               \
    int i0 = PD(q << (t)), i1 = PD(q << ((t) + 1));                             \
    float w0r = twR[i0], w0i = twI[i0];                                         \
    float w1r = twR[i1], w1i = twI[i1];                                         \
    float u0r = x0r + x2r, u0i = x0i + x2i;                                     \
    float d0r = x0r - x2r, d0i = x0i - x2i;                                     \
    float e0r = d0r * w0r - d0i * w0i, e0i = d0r * w0i + d0i * w0r;             \
    float u1r = x1r + x3r, u1i = x1i + x3i;                                     \
    float d1r = x1r - x3r, d1i = x1i - x3i;                                     \
    float e1r = d1r * w0i + d1i * w0r, e1i = -d1r * w0r + d1i * w0i;            \
    sR[a0] = u0r + u1r; sI[a0] = u0i + u1i;                                     \
    float f0r = u0r - u1r, f0i = u0i - u1i;                                     \
    sR[a1] = f0r * w1r - f0i * w1i; sI[a1] = f0r * w1i + f0i * w1r;             \
    sR[a2] = e0r + e1r; sI[a2] = e0i + e1i;                                     \
    float f1r = e0r - e1r, f1i = e0i - e1i;                                     \
    sR[a3] = f1r * w1r - f1i * w1i; sI[a3] = f1r * w1i + f1i * w1r;             \
}

// Fused double DIT stage (t, t+1), inverse.
#define INV_DOUBLE(sR, sI, twR, twI, bi, t)                                     \
{                                                                               \
    const int h = 1 << (t);                                                     \
    int q = (bi) & (h - 1);                                                     \
    int B = (bi) >> (t);                                                        \
    int e0 = B * (h << 2) + q;                                                  \
    int a0 = PD(e0), a1 = PD(e0 + h), a2 = PD(e0 + 2 * h), a3 = PD(e0 + 3 * h); \
    float x0r = sR[a0], x0i = sI[a0], x1r = sR[a1], x1i = sI[a1];               \
    float x2r = sR[a2], x2i = sI[a2], x3r = sR[a3], x3i = sI[a3];               \
    int i0 = PD(q << (9 - (t))), i1 = PD(q << (8 - (t)));                       \
    float c0r = twR[i0], c0i = -twI[i0];                                        \
    float c1r = twR[i1], c1i = -twI[i1];                                        \
    float t1r = c0r * x1r - c0i * x1i, t1i = c0r * x1i + c0i * x1r;             \
    float b0r = x0r + t1r, b0i = x0i + t1i, b1r = x0r - t1r, b1i = x0i - t1i;   \
    float t3r = c0r * x3r - c0i * x3i, t3i = c0r * x3i + c0i * x3r;             \
    float b2r = x2r + t3r, b2i = x2i + t3i, b3r = x2r - t3r, b3i = x2i - t3i;   \
    float t2r = c1r * b2r - c1i * b2i, t2i = c1r * b2i + c1i * b2r;             \
    sR[a0] = b0r + t2r; sI[a0] = b0i + t2i;                                     \
    sR[a2] = b0r - t2r; sI[a2] = b0i - t2i;                                     \
    float gr = -c1i, gi = c1r;                                                  \
    float t4r = gr * b3r - gi * b3i, t4i = gr * b3i + gi * b3r;                 \
    sR[a1] = b1r + t4r; sI[a1] = b1i + t4i;                                     \
    sR[a3] = b1r - t4r; sI[a3] = b1i - t4i;                                     \
}

// ------------------------- fused 3x smoothing + norm partials -------------------------
__global__ void smooth3_kernel(const float* __restrict__ su_ext,
                               const float* __restrict__ sv_ext) {
    __shared__ float t0[38][40];
    __shared__ float t1[38][40];
    __shared__ float red[8];
    int slab = blockIdx.y;
    int fb = slab >> 3, b = slab & 7;
    const float* src = (fb ? sv_ext : su_ext) + (b << 20);
    int tile = blockIdx.x;
    int ty0 = (tile >> 5) << 5;
    int tx0 = (tile & 31) << 5;
    int tid = threadIdx.x;

    for (int i = tid; i < 38 * 38; i += 256) {
        int ly = i / 38, lx = i - ly * 38;
        int gy = (ty0 + ly - 3) & 1023;
        int gx = (tx0 + lx - 3) & 1023;
        t0[ly][lx] = src[(gy << 10) + gx];
    }
    __syncthreads();
    for (int i = tid; i < 36 * 36; i += 256) {
        int ly = i / 36, lx = i - ly * 36;
        ly += 1; lx += 1;
        float c = t0[ly][lx];
        t1[ly][lx] = c + 0.1f * (t0[ly][lx-1] + t0[ly][lx+1] + t0[ly-1][lx] + t0[ly+1][lx] - 4.0f * c);
    }
    __syncthreads();
    for (int i = tid; i < 34 * 34; i += 256) {
        int ly = i / 34, lx = i - ly * 34;
        ly += 2; lx += 2;
        float c = t1[ly][lx];
        t0[ly][lx] = c + 0.1f * (t1[ly][lx-1] + t1[ly][lx+1] + t1[ly-1][lx] + t1[ly+1][lx] - 4.0f * c);
    }
    __syncthreads();
    float ss = 0.0f;
    float* dst = g_fa + fb * BHW + (b << 20);
    for (int i = tid; i < 1024; i += 256) {
        int ly = (i >> 5) + 3, lx = (i & 31) + 3;
        float c = t0[ly][lx];
        float o = c + 0.1f * (t0[ly][lx-1] + t0[ly][lx+1] + t0[ly-1][lx] + t0[ly+1][lx] - 4.0f * c);
        dst[((ty0 + ly - 3) << 10) + (tx0 + lx - 3)] = o;
        ss += o * o;
    }
    float tot = block_reduce_256(ss, red);
    if (tid == 0) g_partials[slab * 1024 + tile] = tot;
}

__global__ void finalize_kernel() {
    int r = blockIdx.x;
    float s = 0.0f;
    for (int i = threadIdx.x; i < 1024; i += 256) s += g_partials[r * 1024 + i];
    __shared__ float red[8];
    float tot = block_reduce_256(s, red);
    if (threadIdx.x == 0) {
        float nrm = sqrtf(tot);
        g_invnorm[r] = 1.0f / fmaxf(nrm, 1e-12f);
    }
}

// ------------------------- main update -------------------------
__global__ void update_kernel(const float* __restrict__ xin,
                              const float* __restrict__ beta) {
    int gid = blockIdx.x * 256 + threadIdx.x;
    int b  = gid >> 20;
    int yx = gid & (HW - 1);
    int y = yx >> 10, x = yx & 1023;

    const float* u = xin + (size_t)(b * 3 + 0) * HW;
    const float* v = xin + (size_t)(b * 3 + 1) * HW;
    const float* p = xin + (size_t)(b * 3 + 2) * HW;

    int ixp = (y << 10) | ((x + 1) & 1023);
    int ixm = (y << 10) | ((x - 1) & 1023);
    int iyp = (((y + 1) & 1023) << 10) | x;
    int iym = (((y - 1) & 1023) << 10) | x;

    float uc = u[yx], uxp = u[ixp], uxm = u[ixm], uyp = u[iyp], uym = u[iym];
    float vc = v[yx], vxp = v[ixp], vxm = v[ixm], vyp = v[iyp], vym = v[iym];
    float pxp = p[ixp], pxm = p[ixm], pyp = p[iyp], pym = p[iym];

    float adv_u = uc * 0.5f * (uxp - uxm) + vc * 0.5f * (uyp - uym);
    float adv_v = uc * 0.5f * (vxp - vxm) + vc * 0.5f * (vyp - vym);
    float lap_u = uxp + uxm + uyp + uym - 4.0f * uc;
    float lap_v = vxp + vxm + vyp + vym - 4.0f * vc;
    float dpdx = 0.5f * (pxp - pxm), dpdy = 0.5f * (pyp - pym);

    float sb = sqrtf(beta[b]);
    float fu = g_fa[(b << 20) + yx] * g_invnorm[b];
    float fv = g_fa[BHW + (b << 20) + yx] * g_invnorm[8 + b];

    g_unew[gid] = uc + DT * (-adv_u + NU * lap_u - dpdx) + sb * fu;
    g_vnew[gid] = vc + DT * (-adv_v + NU * lap_v - dpdy) + sb * fv;
}

// ------------------------- fwd FFT over x: row pair (2yp, 2yp+1) packed -------------------------
// z = d0 + i*d1 -> FFT -> untangle -> store compact half-spectra for both rows.
__global__ void fft_fwd_div_kernel() {
    __shared__ float sR[1056], sI[1056];
    __shared__ float twR[528], twI[528];
    __shared__ float su0[1024], su1[1024];

    int blk = blockIdx.x;                    // b*512 + yp
    int b = blk >> 9, yp = blk & 511;
    int y0 = yp << 1, y1 = y0 + 1;
    int tid = threadIdx.x;
    int ub = b << 20;

    build_tw(twR, twI, tid);
    #pragma unroll
    for (int k = 0; k < 4; k++) {
        int x = tid + k * 256;
        su0[x] = g_unew[ub + (y0 << 10) + x];
        su1[x] = g_unew[ub + (y1 << 10) + x];
    }
    __syncthreads();

    int ym0 = ((y0 - 1) & 1023) << 10, yp0 = y1 << 10;
    int ym1 = y0 << 10,                yp1 = ((y1 + 1) & 1023) << 10;
    #pragma unroll
    for (int k = 0; k < 4; k++) {
        int x = tid + k * 256;
        int xp = (x + 1) & 1023, xm = (x - 1) & 1023;
        float d0 = 0.5f * (su0[xp] - su0[xm]) + 0.5f * (g_vnew[ub + yp0 + x] - g_vnew[ub + ym0 + x]);
        float d1 = 0.5f * (su1[xp] - su1[xm]) + 0.5f * (g_vnew[ub + yp1 + x] - g_vnew[ub + ym1 + x]);
        sR[PD(x)] = d0; sI[PD(x)] = d1;
    }
    __syncthreads();

    #pragma unroll
    for (int t = 0; t < 10; t += 2) {
        FWD_DOUBLE(sR, sI, twR, twI, tid, t);
        __syncthreads();
    }

    // untangle + compact store (only storage j even, plus j==1 i.e. kx=512)
    float2* c0 = g_c1 + b * C1BATCH + y0 * C1ROW;
    float2* c1 = g_c1 + b * C1BATCH + y1 * C1ROW;
    #pragma unroll
    for (int k = 0; k < 4; k++) {
        int j = tid + k * 256;
        bool store = ((j & 1) == 0) || (j == 1);
        if (store) {
            int kk = brev10(j);
            int jm = brev10((1024 - kk) & 1023);
            float Ar = sR[PD(j)],  Ai = sI[PD(j)];
            float Br = sR[PD(jm)], Bi = sI[PD(jm)];
            float s1r = 0.5f * (Ar + Br), s1i = 0.5f * (Ai - Bi);
            float s2r = 0.5f * (Ai + Bi), s2i = 0.5f * (Br - Ar);
            int cc = (j == 1) ? 512 : (j >> 1);
            c0[cc] = make_float2(s1r, s1i);
            c1[cc] = make_float2(s2r, s2i);
        }
    }
}

// ------------------------- fused column pipeline on compact columns -------------------------
#define CS 1057
__global__ void fft_col_poisson_kernel() {
    __shared__ float sR[4 * CS], sI[4 * CS];
    __shared__ float twR[528], twI[528];

    int blk = blockIdx.x;                    // b*129 + g
    int b = blk / 129, g = blk - b * 129;
    int c0 = g << 2;
    int tid = threadIdx.x;
    float2* base = g_c1 + b * C1BATCH;

    build_tw(twR, twI, tid);

    int c = tid & 3, yy = tid >> 2;
    int col = c0 + c;                        // compact column index
    #pragma unroll
    for (int m = 0; m < 16; m++) {
        int y = yy + (m << 6);
        float2 v = base[y * C1ROW + col];
        sR[c * CS + PD(y)] = v.x; sI[c * CS + PD(y)] = v.y;
    }
    __syncthreads();

    int cc = tid >> 6, r = tid & 63;
    float* cR = sR + cc * CS;
    float* cI = sI + cc * CS;

    #pragma unroll
    for (int t = 0; t < 10; t += 2) {
        #pragma unroll
        for (int k = 0; k < 4; k++) {
            int bi = r + (k << 6);
            FWD_DOUBLE(cR, cI, twR, twI, bi, t);
        }
        __syncthreads();
    }

    // Poisson multiplier; spectral kx = brev(2*col) for col<512, 512 otherwise
    int kx = (col >= 512) ? 512 : brev10(col << 1);
    float tkx = (float)min(kx, 1024 - kx);
    #pragma unroll
    for (int m = 0; m < 16; m++) {
        int ry = yy + (m << 6);
        int ky = brev10(ry);
        float tky = (float)min(ky, 1024 - ky);
        float k2 = tkx * tkx + tky * tky;
        float mm = (kx == 0 && ky == 0) ? 0.0f
                 : (-1.0f / (39.47841760435743f * k2)) * (1.0f / 1024.0f);
        int a = c * CS + PD(ry);
        sR[a] *= mm; sI[a] *= mm;
    }
    __syncthreads();

    #pragma unroll
    for (int t = 0; t < 10; t += 2) {
        #pragma unroll
        for (int k = 0; k < 4; k++) {
            int bi = r + (k << 6);
            INV_DOUBLE(cR, cI, twR, twI, bi, t);
        }
        __syncthreads();
    }

    #pragma unroll
    for (int m = 0; m < 16; m++) {
        int y = yy + (m << 6);
        base[y * C1ROW + col] = make_float2(sR[c * CS + PD(y)], sI[c * CS + PD(y)]);
    }
}

// ------------------------- inverse FFT over x: two rows per block via packing -------------------------
__global__ void fft_inv_real_kernel() {
    __shared__ float sR[1056], sI[1056];
    __shared__ float twR[528], twI[528];
    __shared__ float a1R[516], a1I[516], a2R[516], a2I[516];

    int blk = blockIdx.x;                    // b*512 + yp
    int b = blk >> 9, yp = blk & 511;
    int y0 = yp << 1, y1 = y0 + 1;
    int tid = threadIdx.x;

    build_tw(twR, twI, tid);
    const float2* c0 = g_c1 + b * C1BATCH + y0 * C1ROW;
    const float2* c1 = g_c1 + b * C1BATCH + y1 * C1ROW;
    #pragma unroll
    for (int k = 0; k < 2; k++) {
        int cc = tid + k * 256;
        float2 v1 = c0[cc], v2 = c1[cc];
        a1R[cc] = v1.x; a1I[cc] = v1.y;
        a2R[cc] = v2.x; a2I[cc] = v2.y;
    }
    if (tid == 0) {
        float2 v1 = c0[512], v2 = c1[512];
        a1R[512] = v1.x; a1I[512] = v1.y;
        a2R[512] = v2.x; a2I[512] = v2.y;
    }
    __syncthreads();

    // build packed spectrum B = S1 + i*S2 at all storage positions j
    #pragma unroll
    for (int k = 0; k < 4; k++) {
        int j = tid + k * 256;
        float br, bi;
        if ((j & 1) == 0 || j == 1) {
            int cc = (j == 1) ? 512 : (j >> 1);
            br = a1R[cc] - a2I[cc];
            bi = a1I[cc] + a2R[cc];
        } else {
            int kk = brev10(j);                  // > 512
            int jm = brev10(1024 - kk);          // even
            int cc = jm >> 1;
            br = a1R[cc] + a2I[cc];
            bi = -a1I[cc] + a2R[cc];
        }
        sR[PD(j)] = br; sI[PD(j)] = bi;
    }
    __syncthreads();

    #pragma unroll
    for (int t = 0; t < 10; t += 2) {
        INV_DOUBLE(sR, sI, twR, twI, tid, t);
        __syncthreads();
    }

    const float sc = 1.0f / 1024.0f;
    int bb = b << 20;
    #pragma unroll
    for (int k = 0; k < 4; k++) {
        int x = tid + k * 256;
        g_pcorr[bb + (y0 << 10) + x] = sR[PD(x)] * sc;
        g_pcorr[bb + (y1 << 10) + x] = sI[PD(x)] * sc;
    }
}

// ------------------------- final: subtract grad(p_corr), stack output -------------------------
__global__ void final_kernel(const float* __restrict__ xin, float* __restrict__ out) {
    int gid = blockIdx.x * 256 + threadIdx.x;
    int b  = gid >> 20;
    int yx = gid & (HW - 1);
    int y = yx >> 10, x = yx & 1023;

    int ixp = (y << 10) | ((x + 1) & 1023);
    int ixm = (y << 10) | ((x - 1) & 1023);
    int iyp = (((y + 1) & 1023) << 10) | x;
    int iym = (((y - 1) & 1023) << 10) | x;

    int bb = b << 20;
    float pcc = g_pcorr[bb + yx];
    float pxp = g_pcorr[bb + ixp], pxm = g_pcorr[bb + ixm];
    float pyp = g_pcorr[bb + iyp], pym = g_pcorr[bb + iym];

    float uo = g_unew[gid] - 0.5f * (pxp - pxm);
    float vo = g_vnew[gid] - 0.5f * (pyp - pym);
    float po = xin[(size_t)(b * 3 + 2) * HW + yx] + pcc;

    out[(size_t)(b * 3 + 0) * HW + yx] = uo;
    out[(size_t)(b * 3 + 1) * HW + yx] = vo;
    out[(size_t)(b * 3 + 2) * HW + yx] = po;
}

// ------------------------- launch -------------------------
extern "C" void kernel_launch(void* const* d_in, const int* in_sizes, int n_in,
                              void* d_out, int out_size) {
    (void)in_sizes; (void)n_in; (void)out_size;
    const float* x    = (const float*)d_in[0];
    const float* beta = (const float*)d_in[1];
    const float* fu   = (const float*)d_in[2];
    const float* fv   = (const float*)d_in[3];
    float* out = (float*)d_out;

    smooth3_kernel<<<dim3(1024, 16), 256>>>(fu, fv);
    finalize_kernel<<<16, 256>>>();
    update_kernel<<<BHW / 256, 256>>>(x, beta);
    fft_fwd_div_kernel<<<NB * 512, 256>>>();
    fft_col_poisson_kernel<<<NB * 129, 256>>>();
    fft_inv_real_kernel<<<NB * 512, 256>>>();
    final_kernel<<<BHW / 256, 256>>>(x, out);
}